// round 6
// baseline (speedup 1.0000x reference)
#include <cuda_runtime.h>
#include <cstdint>
#include <cstddef>

#define S_  2048
#define D_  64
#define H_  16
#define B_  2
#define BH_ 32
#define TQ  128
#define TK  128
#define NKT (S_/TK)

// scratch for per-row softmax stats (allocation-free rule: device globals)
__device__ float g_m[BH_*S_];
__device__ float g_l[BH_*S_];

__device__ __forceinline__ float neg_inf() { return __int_as_float(0xff800000u); }

// ---------------------------------------------------------------------------
// Pass 1: raw scores = (Q K^T + adj) * scale, masked -> -inf.
// Writes raw scores into the p_attn output region; computes per-row online
// max (m) and sumexp (l) entirely within the block (block spans full K range).
// Mask is read as 32-bit words, nonzero == masked (works for int32 AND fp32).
// ---------------------------------------------------------------------------
__global__ __launch_bounds__(256, 2) void scores_kernel(
    const float* __restrict__ Q, const float* __restrict__ Kp,
    const unsigned int* __restrict__ mask, const float* __restrict__ adj,
    float* __restrict__ Praw)
{
    extern __shared__ float sm[];
    float* Qs  = sm;                 // [64][132] transposed: Qs[d*132 + r]
    float* Ks  = Qs + 64*132;        // [64][132] transposed
    float* red = Ks + 64*132;        // [128][17]
    float* m_s = red + 128*17;       // [128]
    float* l_s = m_s + 128;          // [128]

    const int tid = threadIdx.x;
    const int ty  = tid >> 4;
    const int tx  = tid & 15;
    const int bh  = blockIdx.y;
    const int b   = bh >> 4;
    const int q0  = blockIdx.x * TQ;

    // load Q tile transposed (coalesced gmem, 4-way STS conflict acceptable)
    const float* Qg = Q + ((size_t)bh * S_ + q0) * D_;
    #pragma unroll
    for (int it = 0; it < 32; ++it) {
        int idx = it*256 + tid;
        int r = idx >> 6, d = idx & 63;
        Qs[d*132 + r] = Qg[idx];
    }
    if (tid < TQ) { m_s[tid] = -3.0e38f; l_s[tid] = 0.f; }

    float acc[8][8];

    for (int kt = 0; kt < NKT; ++kt) {
        const int k0 = kt * TK;
        const float* Kg = Kp + ((size_t)bh * S_ + k0) * D_;
        #pragma unroll
        for (int it = 0; it < 32; ++it) {
            int idx = it*256 + tid;
            int r = idx >> 6, d = idx & 63;
            Ks[d*132 + r] = Kg[idx];
        }
        __syncthreads();   // Ks (and, on kt==0, Qs/m_s/l_s) visible

        #pragma unroll
        for (int i = 0; i < 8; ++i)
            #pragma unroll
            for (int j = 0; j < 8; ++j) acc[i][j] = 0.f;

        #pragma unroll 8
        for (int d = 0; d < 64; ++d) {
            float4 a0 = *(const float4*)(Qs + d*132 + ty*8);
            float4 a1 = *(const float4*)(Qs + d*132 + ty*8 + 4);
            float4 b0 = *(const float4*)(Ks + d*132 + tx*8);
            float4 b1 = *(const float4*)(Ks + d*132 + tx*8 + 4);
            float a[8]  = {a0.x,a0.y,a0.z,a0.w,a1.x,a1.y,a1.z,a1.w};
            float bb[8] = {b0.x,b0.y,b0.z,b0.w,b1.x,b1.y,b1.z,b1.w};
            #pragma unroll
            for (int i = 0; i < 8; ++i)
                #pragma unroll
                for (int j = 0; j < 8; ++j)
                    acc[i][j] = fmaf(a[i], bb[j], acc[i][j]);
        }

        // epilogue: bias + scale + mask, per-row partial max
        #pragma unroll
        for (int i = 0; i < 8; ++i) {
            const int q = q0 + ty*8 + i;
            const float* arow = adj + ((size_t)bh*S_ + q)*S_ + k0 + tx*8;
            float4 A0 = *(const float4*)arow;
            float4 A1 = *(const float4*)(arow + 4);
            const unsigned int* mrow = mask + ((size_t)b*S_ + q)*S_ + k0 + tx*8;
            uint4 M0 = *(const uint4*)mrow;
            uint4 M1 = *(const uint4*)(mrow + 4);
            float av[8] = {A0.x,A0.y,A0.z,A0.w,A1.x,A1.y,A1.z,A1.w};
            unsigned mm[8] = {M0.x,M0.y,M0.z,M0.w,M1.x,M1.y,M1.z,M1.w};
            float pm = -3.0e38f;
            #pragma unroll
            for (int j = 0; j < 8; ++j) {
                float sc = (acc[i][j] + av[j]) * 0.125f;
                if (mm[j] != 0u) sc = neg_inf();
                acc[i][j] = sc;
                pm = fmaxf(pm, sc);
            }
            red[(ty*8+i)*17 + tx] = pm;
        }
        __syncthreads();

        if (tid < TQ) {
            float tm = red[tid*17];
            #pragma unroll
            for (int t = 1; t < 16; ++t) tm = fmaxf(tm, red[tid*17 + t]);
            float mo = m_s[tid];
            float mn = fmaxf(mo, tm);
            l_s[tid] *= __expf(mo - mn);   // mo,mn finite -> safe
            m_s[tid]  = mn;
        }
        __syncthreads();

        // sumexp partials + write raw scores
        #pragma unroll
        for (int i = 0; i < 8; ++i) {
            const int q = q0 + ty*8 + i;
            const float mrow = m_s[ty*8 + i];
            float es = 0.f;
            #pragma unroll
            for (int j = 0; j < 8; ++j) es += __expf(acc[i][j] - mrow);
            red[(ty*8+i)*17 + tx] = es;
            float* prow = Praw + ((size_t)bh*S_ + q)*S_ + k0 + tx*8;
            *(float4*)prow     = make_float4(acc[i][0],acc[i][1],acc[i][2],acc[i][3]);
            *(float4*)(prow+4) = make_float4(acc[i][4],acc[i][5],acc[i][6],acc[i][7]);
        }
        __syncthreads();

        if (tid < TQ) {
            float es = 0.f;
            #pragma unroll
            for (int t = 0; t < 16; ++t) es += red[tid*17 + t];
            l_s[tid] += es;
        }
        __syncthreads();  // also guards Ks/red overwrite next iteration
    }

    if (tid < TQ) {
        g_m[bh*S_ + q0 + tid] = m_s[tid];
        g_l[bh*S_ + q0 + tid] = l_s[tid];
    }
}

// ---------------------------------------------------------------------------
// Pass 2: p = exp(s - m) / l  (in-place in the p_attn region), fused with
// out = P @ V.
// ---------------------------------------------------------------------------
__global__ __launch_bounds__(256, 2) void pv_kernel(
    float* __restrict__ P,          // in: raw scores, out: normalized p_attn
    const float* __restrict__ V,
    float* __restrict__ Out)
{
    extern __shared__ float sm[];
    float* Ps   = sm;               // [128][132] transposed: Ps[k*132 + r]
    float* Vs   = Ps + 128*132;     // [128][68]
    float* m_s  = Vs + 128*68;      // [128]
    float* il_s = m_s + 128;        // [128]

    const int tid = threadIdx.x;
    const int ty  = tid >> 4;
    const int tx  = tid & 15;
    const int bh  = blockIdx.y;
    const int q0  = blockIdx.x * TQ;

    if (tid < TQ) {
        m_s[tid]  = g_m[bh*S_ + q0 + tid];
        il_s[tid] = 1.0f / g_l[bh*S_ + q0 + tid];
    }

    float acc[8][4];
    #pragma unroll
    for (int i = 0; i < 8; ++i)
        #pragma unroll
        for (int j = 0; j < 4; ++j) acc[i][j] = 0.f;

    for (int kt = 0; kt < NKT; ++kt) {
        const int k0 = kt * TK;
        __syncthreads();   // protect Ps/Vs reuse; first iter: m_s/il_s visible

        const float* Vg = V + ((size_t)bh*S_ + k0) * D_;
        #pragma unroll
        for (int it = 0; it < 32; ++it) {
            int idx = it*256 + tid;
            int r = idx >> 6, d = idx & 63;
            Vs[r*68 + d] = Vg[idx];
        }

        float* Pg = P + ((size_t)bh*S_ + q0)*S_ + k0;   // row stride S_
        #pragma unroll
        for (int it = 0; it < 64; ++it) {
            int lin = it*256 + tid;
            int r = lin >> 7, k = lin & 127;
            float s = Pg[(size_t)r * S_ + k];
            float p = __expf(s - m_s[r]) * il_s[r];
            Pg[(size_t)r * S_ + k] = p;
            Ps[k*132 + r] = p;
        }
        __syncthreads();

        #pragma unroll 8
        for (int k = 0; k < 128; ++k) {
            float4 a0 = *(const float4*)(Ps + k*132 + ty*8);
            float4 a1 = *(const float4*)(Ps + k*132 + ty*8 + 4);
            float4 bv = *(const float4*)(Vs + k*68 + tx*4);
            float a[8]  = {a0.x,a0.y,a0.z,a0.w,a1.x,a1.y,a1.z,a1.w};
            float bb[4] = {bv.x,bv.y,bv.z,bv.w};
            #pragma unroll
            for (int i = 0; i < 8; ++i)
                #pragma unroll
                for (int j = 0; j < 4; ++j)
                    acc[i][j] = fmaf(a[i], bb[j], acc[i][j]);
        }
    }

    #pragma unroll
    for (int i = 0; i < 8; ++i) {
        float* orow = Out + ((size_t)bh*S_ + q0 + ty*8 + i)*D_ + tx*4;
        *(float4*)orow = make_float4(acc[i][0], acc[i][1], acc[i][2], acc[i][3]);
    }
}

// ---------------------------------------------------------------------------

static const int SMEM_A = (2*64*132 + 128*17 + 2*128) * (int)sizeof(float); // 77312
static const int SMEM_C = (128*132 + 128*68 + 2*128) * (int)sizeof(float);  // 103424

extern "C" void kernel_launch(void* const* d_in, const int* in_sizes, int n_in,
                              void* d_out, int out_size) {
    const float*        Q    = (const float*)d_in[0];
    const float*        K    = (const float*)d_in[1];
    const float*        V    = (const float*)d_in[2];
    const unsigned int* mask = (const unsigned int*)d_in[3];
    const float*        adj  = (const float*)d_in[4];

    float* out = (float*)d_out;                       // (B,H,S,D) first
    float* P   = out + (size_t)B_ * H_ * S_ * D_;     // then (B,H,S,S)

    cudaFuncSetAttribute(scores_kernel, cudaFuncAttributeMaxDynamicSharedMemorySize, SMEM_A);
    cudaFuncSetAttribute(pv_kernel,     cudaFuncAttributeMaxDynamicSharedMemorySize, SMEM_C);

    dim3 grid(S_/TQ, BH_);   // (16, 32)
    scores_kernel<<<grid, 256, SMEM_A>>>(Q, K, mask, adj, P);
    pv_kernel<<<grid, 256, SMEM_C>>>(P, V, out);
}

// round 12
// speedup vs baseline: 2.5622x; 2.5622x over previous
#include <cuda_runtime.h>
#include <cuda_bf16.h>
#include <cstdint>
#include <cstddef>

#define S_  2048
#define D_  64
#define H_  16
#define B_  2
#define BH_ 32
#define TQ  128
#define TK  128
#define NKT (S_/TK)
#define TK2 64
#define NKT2 (S_/TK2)

// ---------------- device scratch (allocation-free rule) ----------------
__device__ float g_m[BH_*S_];
__device__ float g_l[BH_*S_];
__device__ __nv_bfloat16 g_vthi[BH_*D_*S_];   // V^T per bh: [bh][d][k]
__device__ __nv_bfloat16 g_vtlo[BH_*D_*S_];

// ---------------- helpers ----------------
__device__ __forceinline__ unsigned smem_u32(const void* p){
    unsigned a;
    asm("{ .reg .u64 t; cvta.to.shared.u64 t, %1; cvt.u32.u64 %0, t; }":"=r"(a):"l"(p));
    return a;
}
__device__ __forceinline__ void ldsm_x4(unsigned& a0,unsigned& a1,unsigned& a2,unsigned& a3, unsigned addr){
    asm volatile("ldmatrix.sync.aligned.m8n8.x4.shared.b16 {%0,%1,%2,%3}, [%4];"
        : "=r"(a0),"=r"(a1),"=r"(a2),"=r"(a3) : "r"(addr));
}
__device__ __forceinline__ void ldsm_x2(unsigned& b0,unsigned& b1, unsigned addr){
    asm volatile("ldmatrix.sync.aligned.m8n8.x2.shared.b16 {%0,%1}, [%2];"
        : "=r"(b0),"=r"(b1) : "r"(addr));
}
__device__ __forceinline__ void mma16816(float* c, unsigned a0,unsigned a1,unsigned a2,unsigned a3,
                                         unsigned b0,unsigned b1){
    asm volatile("mma.sync.aligned.m16n8k16.row.col.f32.bf16.bf16.f32 "
        "{%0,%1,%2,%3}, {%4,%5,%6,%7}, {%8,%9}, {%0,%1,%2,%3};"
        : "+f"(c[0]),"+f"(c[1]),"+f"(c[2]),"+f"(c[3])
        : "r"(a0),"r"(a1),"r"(a2),"r"(a3),"r"(b0),"r"(b1));
}

// convert 8 consecutive fp32 -> packed bf16 hi (16B) and lo (16B)
__device__ __forceinline__ void cvt_hilo8(float4 x0, float4 x1, uint4& hv, uint4& lv){
    float v[8] = {x0.x,x0.y,x0.z,x0.w,x1.x,x1.y,x1.z,x1.w};
    unsigned hh[4], ll[4];
    #pragma unroll
    for (int i = 0; i < 4; ++i){
        float a = v[2*i], bq = v[2*i+1];
        __nv_bfloat16 ha = __float2bfloat16(a), hb = __float2bfloat16(bq);
        float la = a - __bfloat162float(ha);
        float lb = bq - __bfloat162float(hb);
        __nv_bfloat16 hla = __float2bfloat16(la), hlb = __float2bfloat16(lb);
        hh[i] = ((unsigned)__bfloat16_as_ushort(hb) << 16) | (unsigned)__bfloat16_as_ushort(ha);
        ll[i] = ((unsigned)__bfloat16_as_ushort(hlb) << 16) | (unsigned)__bfloat16_as_ushort(hla);
    }
    hv = make_uint4(hh[0],hh[1],hh[2],hh[3]);
    lv = make_uint4(ll[0],ll[1],ll[2],ll[3]);
}

// ---------------- kernel 0: V transpose + hi/lo split ----------------
__global__ __launch_bounds__(256) void vsplit_kernel(const float* __restrict__ V){
    __shared__ float ts[64][69];
    const int tid = threadIdx.x;
    const int bh = blockIdx.y, k0 = blockIdx.x * 64;
    #pragma unroll
    for (int it = 0; it < 16; ++it){
        int lin = it*256 + tid;
        int kk = lin >> 6, d = lin & 63;
        ts[kk][d] = V[((size_t)bh*S_ + k0 + kk)*D_ + d];
    }
    __syncthreads();
    #pragma unroll
    for (int it = 0; it < 16; ++it){
        int lin = it*256 + tid;
        int d = lin >> 6, kk = lin & 63;
        float v = ts[kk][d];
        __nv_bfloat16 h = __float2bfloat16(v);
        __nv_bfloat16 l = __float2bfloat16(v - __bfloat162float(h));
        size_t o = ((size_t)bh*D_ + d)*S_ + k0 + kk;
        g_vthi[o] = h;
        g_vtlo[o] = l;
    }
}

// ---------------- pass 1: scores via mma.sync bf16x3 ----------------
// smem (bf16, row stride 72 => 144B => 4-bank shift, ldmatrix conflict-free)
#define SQ1   72
#define P1_QH 0
#define P1_QL 18432
#define P1_KH 36864
#define P1_KL 55296
#define SMEM1 73728

__global__ __launch_bounds__(256, 2) void scores_mma_kernel(
    const float* __restrict__ Q, const float* __restrict__ Kp,
    const unsigned* __restrict__ mask, const float* __restrict__ adj,
    float* __restrict__ P)
{
    extern __shared__ char smem[];
    const unsigned sb = smem_u32(smem);
    const int tid = threadIdx.x, w = tid >> 5, l = tid & 31;
    const int bh = blockIdx.y, b = bh >> 4;
    const int q0 = blockIdx.x * TQ;

    // Q tile -> bf16 hi/lo
    const float* Qg = Q + ((size_t)bh*S_ + q0)*D_;
    #pragma unroll
    for (int it = 0; it < 4; ++it){
        int lin = it*256 + tid;
        int row = lin >> 3, g = lin & 7;
        const float4* qp = (const float4*)(Qg + row*64 + g*8);
        uint4 hv, lv; cvt_hilo8(qp[0], qp[1], hv, lv);
        *(uint4*)(smem + P1_QH + (row*SQ1 + g*8)*2) = hv;
        *(uint4*)(smem + P1_QL + (row*SQ1 + g*8)*2) = lv;
    }

    // ldmatrix lane addressing
    const int la_row = 16*w + (l & 15);
    const int la_k8  = (l >> 4) * 8;
    const int lb_row = l & 7;              // + 8*nt
    const int lb_k8  = ((l >> 3) & 1) * 8;
    const int qr = l >> 2;                 // 0..7
    const int ci = l & 3;

    float m_run[2] = {-3.0e38f, -3.0e38f};
    float l_run[2] = {0.f, 0.f};

    for (int kt = 0; kt < NKT; ++kt){
        const int k0 = kt * TK;
        const float* Kg = Kp + ((size_t)bh*S_ + k0)*D_;
        #pragma unroll
        for (int it = 0; it < 4; ++it){
            int lin = it*256 + tid;
            int row = lin >> 3, g = lin & 7;
            const float4* kp = (const float4*)(Kg + row*64 + g*8);
            uint4 hv, lv; cvt_hilo8(kp[0], kp[1], hv, lv);
            *(uint4*)(smem + P1_KH + (row*SQ1 + g*8)*2) = hv;
            *(uint4*)(smem + P1_KL + (row*SQ1 + g*8)*2) = lv;
        }
        __syncthreads();

        float acc[16][4];
        #pragma unroll
        for (int nt = 0; nt < 16; ++nt)
            #pragma unroll
            for (int j = 0; j < 4; ++j) acc[nt][j] = 0.f;

        #pragma unroll
        for (int kk = 0; kk < 4; ++kk){
            const int koffA = kk*16 + la_k8;
            unsigned ah0,ah1,ah2,ah3, al0,al1,al2,al3;
            ldsm_x4(ah0,ah1,ah2,ah3, sb + P1_QH + (la_row*SQ1 + koffA)*2);
            ldsm_x4(al0,al1,al2,al3, sb + P1_QL + (la_row*SQ1 + koffA)*2);
            const int koffB = kk*16 + lb_k8;
            #pragma unroll
            for (int nt = 0; nt < 16; ++nt){
                unsigned bh0,bh1, bl0,bl1;
                ldsm_x2(bh0,bh1, sb + P1_KH + ((8*nt + lb_row)*SQ1 + koffB)*2);
                ldsm_x2(bl0,bl1, sb + P1_KL + ((8*nt + lb_row)*SQ1 + koffB)*2);
                mma16816(acc[nt], ah0,ah1,ah2,ah3, bh0,bh1);
                mma16816(acc[nt], ah0,ah1,ah2,ah3, bl0,bl1);
                mma16816(acc[nt], al0,al1,al2,al3, bh0,bh1);
            }
        }
        __syncthreads();   // smem K tiles free for next iteration

        // epilogue in fragment layout; quad shfl reductions
        #pragma unroll
        for (int h = 0; h < 2; ++h){
            const int row = 16*w + qr + 8*h;
            const float2* ap = (const float2*)(adj + ((size_t)bh*S_ + q0 + row)*S_ + k0);
            const uint2*  mp = (const uint2*) (mask + ((size_t)b*S_  + q0 + row)*S_ + k0);
            float2*       pp = (float2*)(P + ((size_t)bh*S_ + q0 + row)*S_ + k0);
            float s0[16], s1[16];
            float pm = -3.0e38f;
            #pragma unroll
            for (int nt = 0; nt < 16; ++nt){
                float2 a = ap[ci + 4*nt];
                uint2 mv = mp[ci + 4*nt];
                float x0 = (acc[nt][2*h]   + a.x) * 0.125f;
                float x1 = (acc[nt][2*h+1] + a.y) * 0.125f;
                if (mv.x) x0 = __int_as_float(0xff800000u);
                if (mv.y) x1 = __int_as_float(0xff800000u);
                s0[nt] = x0; s1[nt] = x1;
                pm = fmaxf(pm, fmaxf(x0, x1));
            }
            pm = fmaxf(pm, __shfl_xor_sync(0xffffffffu, pm, 1));
            pm = fmaxf(pm, __shfl_xor_sync(0xffffffffu, pm, 2));
            float mn = fmaxf(m_run[h], pm);
            float es = 0.f;
            #pragma unroll
            for (int nt = 0; nt < 16; ++nt)
                es += __expf(s0[nt]-mn) + __expf(s1[nt]-mn);
            es += __shfl_xor_sync(0xffffffffu, es, 1);
            es += __shfl_xor_sync(0xffffffffu, es, 2);
            l_run[h] = l_run[h]*__expf(m_run[h]-mn) + es;
            m_run[h] = mn;
            #pragma unroll
            for (int nt = 0; nt < 16; ++nt)
                pp[ci + 4*nt] = make_float2(s0[nt], s1[nt]);
        }
    }

    if (ci == 0){
        #pragma unroll
        for (int h = 0; h < 2; ++h){
            const int row = 16*w + qr + 8*h;
            g_m[bh*S_ + q0 + row] = m_run[h];
            g_l[bh*S_ + q0 + row] = l_run[h];
        }
    }
}

// ---------------- pass 2: normalize + P@V via mma.sync bf16x3 ----------------
#define P2_PH 0
#define P2_PL 18432
#define P2_VH 36864
#define P2_VL 46080
#define P2_MS 55296
#define P2_IL 55808
#define SMEM2 56320

__global__ __launch_bounds__(256, 2) void pv_mma_kernel(
    float* __restrict__ P, float* __restrict__ Out)
{
    extern __shared__ char smem[];
    const unsigned sb = smem_u32(smem);
    const int tid = threadIdx.x, w = tid >> 5, l = tid & 31;
    const int bh = blockIdx.y;
    const int q0 = blockIdx.x * TQ;

    float* m_s  = (float*)(smem + P2_MS);
    float* il_s = (float*)(smem + P2_IL);
    if (tid < 128){
        m_s[tid]  = g_m[bh*S_ + q0 + tid];
        il_s[tid] = 1.0f / g_l[bh*S_ + q0 + tid];
    }

    const __nv_bfloat16* vh = g_vthi + (size_t)bh*D_*S_;
    const __nv_bfloat16* vl = g_vtlo + (size_t)bh*D_*S_;

    const int la_row = 16*w + (l & 15);
    const int la_k8  = (l >> 4) * 8;
    const int lb_row = l & 7;
    const int lb_k8  = ((l >> 3) & 1) * 8;
    const int qr = l >> 2;
    const int ci = l & 3;

    float acc[8][4];
    #pragma unroll
    for (int nt = 0; nt < 8; ++nt)
        #pragma unroll
        for (int j = 0; j < 4; ++j) acc[nt][j] = 0.f;

    __syncthreads();   // m_s/il_s visible

    for (int kt = 0; kt < NKT2; ++kt){
        const int k0 = kt * TK2;
        // V tiles [64 d][64 k] hi/lo
        #pragma unroll
        for (int it = 0; it < 2; ++it){
            int lin = it*256 + tid;        // 0..511
            int row = lin >> 3, c8 = lin & 7;
            size_t src = (size_t)row*S_ + k0 + c8*8;
            *(uint4*)(smem + P2_VH + (row*SQ1 + c8*8)*2) = *(const uint4*)(vh + src);
            *(uint4*)(smem + P2_VL + (row*SQ1 + c8*8)*2) = *(const uint4*)(vl + src);
        }
        // P tile: normalize in place + convert hi/lo to smem
        #pragma unroll
        for (int it = 0; it < 4; ++it){
            int lin = it*256 + tid;        // 0..1023
            int row = lin >> 3, g = lin & 7;
            float* sp = P + ((size_t)bh*S_ + q0 + row)*S_ + k0 + g*8;
            float4 x0 = ((const float4*)sp)[0];
            float4 x1 = ((const float4*)sp)[1];
            float mm = m_s[row], il = il_s[row];
            float4 p0 = make_float4(__expf(x0.x-mm)*il, __expf(x0.y-mm)*il,
                                    __expf(x0.z-mm)*il, __expf(x0.w-mm)*il);
            float4 p1 = make_float4(__expf(x1.x-mm)*il, __expf(x1.y-mm)*il,
                                    __expf(x1.z-mm)*il, __expf(x1.w-mm)*il);
            ((float4*)sp)[0] = p0;
            ((float4*)sp)[1] = p1;
            uint4 hv, lv; cvt_hilo8(p0, p1, hv, lv);
            *(uint4*)(smem + P2_PH + (row*SQ1 + g*8)*2) = hv;
            *(uint4*)(smem + P2_PL + (row*SQ1 + g*8)*2) = lv;
        }
        __syncthreads();

        #pragma unroll
        for (int kk = 0; kk < 4; ++kk){
            const int koffA = kk*16 + la_k8;
            unsigned ah0,ah1,ah2,ah3, al0,al1,al2,al3;
            ldsm_x4(ah0,ah1,ah2,ah3, sb + P2_PH + (la_row*SQ1 + koffA)*2);
            ldsm_x4(al0,al1,al2,al3, sb + P2_PL + (la_row*SQ1 + koffA)*2);
            const int koffB = kk*16 + lb_k8;
            #pragma unroll
            for (int nt = 0; nt < 8; ++nt){
                unsigned bh0,bh1, bl0,bl1;
                ldsm_x2(bh0,bh1, sb + P2_VH + ((8*nt + lb_row)*SQ1 + koffB)*2);
                ldsm_x2(bl0,bl1, sb + P2_VL + ((8*nt + lb_row)*SQ1 + koffB)*2);
                mma16816(acc[nt], ah0,ah1,ah2,ah3, bh0,bh1);
                mma16816(acc[nt], ah0,ah1,ah2,ah3, bl0,bl1);
                mma16816(acc[nt], al0,al1,al2,al3, bh0,bh1);
            }
        }
        __syncthreads();   // smem free for next tile
    }

    #pragma unroll
    for (int h = 0; h < 2; ++h){
        const int row = 16*w + qr + 8*h;
        float2* op = (float2*)(Out + ((size_t)bh*S_ + q0 + row)*D_);
        #pragma unroll
        for (int nt = 0; nt < 8; ++nt)
            op[ci + 4*nt] = make_float2(acc[nt][2*h], acc[nt][2*h+1]);
    }
}

// ---------------------------------------------------------------------------
extern "C" void kernel_launch(void* const* d_in, const int* in_sizes, int n_in,
                              void* d_out, int out_size) {
    const float*    Q    = (const float*)d_in[0];
    const float*    K    = (const float*)d_in[1];
    const float*    V    = (const float*)d_in[2];
    const unsigned* mask = (const unsigned*)d_in[3];
    const float*    adj  = (const float*)d_in[4];

    float* out = (float*)d_out;                       // (B,H,S,D)
    float* P   = out + (size_t)B_ * H_ * S_ * D_;     // (B,H,S,S)

    cudaFuncSetAttribute(scores_mma_kernel, cudaFuncAttributeMaxDynamicSharedMemorySize, SMEM1);
    cudaFuncSetAttribute(pv_mma_kernel,     cudaFuncAttributeMaxDynamicSharedMemorySize, SMEM2);

    vsplit_kernel<<<dim3(S_/64, BH_), 256>>>(V);
    dim3 grid(S_/TQ, BH_);   // (16, 32)
    scores_mma_kernel<<<grid, 256, SMEM1>>>(Q, K, mask, adj, P);
    pv_mma_kernel<<<grid, 256, SMEM2>>>(P, out);
}